// round 1
// baseline (speedup 1.0000x reference)
#include <cuda_runtime.h>

// CreateOverlappingWindows: x (B=64, T=2000, C=26) fp32 ->
// out (B*T, WINDOW*C) with WINDOW=19 (N_CONTEXT=9), zero-padded at edges.
//
// out[(b*T+t), w*C + c] = (0 <= t+w-9 < T) ? x[b, t+w-9, c] : 0
//
// Memory-bound: 253 MB stores + 13 MB loads (input lives in L2 across the
// 19x reuse). One block per (t, b) output row; 247 threads each write one
// float2 (19*13 = 247 float2 per row). Fully coalesced stores.

#define B_DIM 64
#define T_DIM 2000
#define C_DIM 26
#define NCTX 9
#define WINDOW 19
#define ROW_F2 (WINDOW * (C_DIM / 2))   // 247 float2 per output row

__global__ __launch_bounds__(256) void overlap_windows_kernel(
    const float* __restrict__ x, float* __restrict__ out)
{
    const int j2 = threadIdx.x;            // 0..255, active < 247
    if (j2 >= ROW_F2) return;

    const int t = blockIdx.x;              // 0..1999
    const int b = blockIdx.y;              // 0..63

    // w = window position (0..18), c2 = float2 index within channel dim (0..12)
    const int w  = j2 / 13;
    const int c2 = j2 - w * 13;

    const int tp = t + w - NCTX;

    float2 v = make_float2(0.0f, 0.0f);
    if ((unsigned)tp < (unsigned)T_DIM) {
        v = *reinterpret_cast<const float2*>(
            x + ((size_t)b * T_DIM + tp) * C_DIM + c2 * 2);
    }

    const size_t row = (size_t)b * T_DIM + t;
    *reinterpret_cast<float2*>(
        out + row * (WINDOW * C_DIM) + w * C_DIM + c2 * 2) = v;
}

extern "C" void kernel_launch(void* const* d_in, const int* in_sizes, int n_in,
                              void* d_out, int out_size)
{
    const float* x = (const float*)d_in[0];
    float* out = (float*)d_out;

    dim3 grid(T_DIM, B_DIM);
    dim3 block(256);
    overlap_windows_kernel<<<grid, block>>>(x, out);
}

// round 2
// speedup vs baseline: 2.0693x; 2.0693x over previous
#include <cuda_runtime.h>

// CreateOverlappingWindows: x (B=64, T=2000, C=26) fp32 ->
// out (B*T, 19*26) with WINDOW=19 (N_CONTEXT=9), zero-padded edges.
//
// Smem-staged tiler. Block = 100 consecutive t rows of one batch.
// Stage x rows [t0-9, t0+109) (zero-padded) into smem, then emit the
// 100*494-float output tile with flat, fully-coalesced float4 stores.
//
// Index identity: output element fe (flat within tile), trow = fe/494,
// k = fe % 494, w = k/26, c = k%26 -> smem src = (trow+w)*26 + c
//                                             = trow*26 + k = fe - trow*468.

#define B_DIM   64
#define T_DIM   2000
#define C_DIM   26
#define NCTX    9
#define WINDOW  19
#define ROW_F   (WINDOW * C_DIM)          // 494 floats per output row
#define TILE_T  100                        // output rows per block
#define SM_ROWS (TILE_T + 2 * NCTX)        // 118 input rows staged
#define SM_F    (SM_ROWS * C_DIM)          // 3068 floats
#define TILE_F  (TILE_T * ROW_F)           // 49400 floats out per tile
#define TILE_F4 (TILE_F / 4)               // 12350 float4
#define NTHREADS 256

__global__ __launch_bounds__(NTHREADS) void overlap_windows_kernel(
    const float* __restrict__ x, float* __restrict__ out)
{
    __shared__ float sm[SM_F];

    const int tile = blockIdx.x;          // 0..19
    const int b    = blockIdx.y;          // 0..63
    const int t0   = tile * TILE_T;
    const int tid  = threadIdx.x;

    // ---- Phase 1: stage input rows [t0-9, t0+109) into smem (zero-padded)
    // 3068 floats = 1534 float2; 13 float2 per input row.
    #pragma unroll
    for (int i = tid; i < SM_F / 2; i += NTHREADS) {
        const int lr = i / 13;            // local row 0..117
        const int c2 = i - lr * 13;
        const int t  = t0 - NCTX + lr;
        float2 v = make_float2(0.0f, 0.0f);
        if ((unsigned)t < (unsigned)T_DIM) {
            v = *reinterpret_cast<const float2*>(
                x + ((size_t)b * T_DIM + t) * C_DIM + c2 * 2);
        }
        *reinterpret_cast<float2*>(sm + i * 2) = v;
    }
    __syncthreads();

    // ---- Phase 2: emit the output tile, float4 flat stores
    float* tout = out + ((size_t)b * T_DIM + t0) * ROW_F;   // 16B aligned

    for (int i4 = tid; i4 < TILE_F4; i4 += NTHREADS) {
        const int f = i4 * 4;
        float4 v;
        {
            const int fe = f + 0;
            const int trow = fe / ROW_F;
            v.x = sm[fe - trow * (ROW_F - C_DIM)];
        }
        {
            const int fe = f + 1;
            const int trow = fe / ROW_F;
            v.y = sm[fe - trow * (ROW_F - C_DIM)];
        }
        {
            const int fe = f + 2;
            const int trow = fe / ROW_F;
            v.z = sm[fe - trow * (ROW_F - C_DIM)];
        }
        {
            const int fe = f + 3;
            const int trow = fe / ROW_F;
            v.w = sm[fe - trow * (ROW_F - C_DIM)];
        }
        *reinterpret_cast<float4*>(tout + f) = v;
    }
}

extern "C" void kernel_launch(void* const* d_in, const int* in_sizes, int n_in,
                              void* d_out, int out_size)
{
    const float* x = (const float*)d_in[0];
    float* out = (float*)d_out;

    dim3 grid(T_DIM / TILE_T, B_DIM);     // 20 x 64 = 1280 blocks
    overlap_windows_kernel<<<grid, NTHREADS>>>(x, out);
}

// round 3
// speedup vs baseline: 2.2509x; 1.0878x over previous
#include <cuda_runtime.h>

// CreateOverlappingWindows: x (B=64, T=2000, C=26) fp32 ->
// out (B*T, 19*26) with WINDOW=19 (N_CONTEXT=9), zero-padded edges.
//
// Smem-staged tiler, float2 granularity throughout.
// ROW_F=494 is even, so a float2 at even flat offset never crosses an
// output-row boundary -> crossing-free LDS.64 reads (2-way conflict max
// = smem crossbar peak) and coalesced STG.64 streaming stores.
//
// Index identity: flat tile offset fe, trow = fe/494,
//   smem src = fe - trow*468  (468 = 494 - 26).

#define B_DIM   64
#define T_DIM   2000
#define C_DIM   26
#define NCTX    9
#define WINDOW  19
#define ROW_F   (WINDOW * C_DIM)          // 494 floats per output row
#define TILE_T  50                         // output rows per block
#define SM_ROWS (TILE_T + 2 * NCTX)        // 68 input rows staged
#define SM_F    (SM_ROWS * C_DIM)          // 1768 floats (7.07 KB)
#define TILE_F2 (TILE_T * ROW_F / 2)       // 12350 float2 out per tile
#define NTHREADS 256

__global__ __launch_bounds__(NTHREADS) void overlap_windows_kernel(
    const float* __restrict__ x, float* __restrict__ out)
{
    __shared__ __align__(16) float sm[SM_F];

    const int tile = blockIdx.x;          // 0..39
    const int b    = blockIdx.y;          // 0..63
    const int t0   = tile * TILE_T;
    const int tid  = threadIdx.x;

    // ---- Phase 1: stage x rows [t0-9, t0+59) into smem, zero-padded.
    // 884 float2, 13 float2 per input row.
    #pragma unroll
    for (int i = tid; i < SM_F / 2; i += NTHREADS) {
        const int lr = i / 13;            // local row 0..67
        const int c2 = i - lr * 13;
        const int t  = t0 - NCTX + lr;
        float2 v = make_float2(0.0f, 0.0f);
        if ((unsigned)t < (unsigned)T_DIM) {
            v = *reinterpret_cast<const float2*>(
                x + ((size_t)b * T_DIM + t) * C_DIM + c2 * 2);
        }
        *reinterpret_cast<float2*>(sm + i * 2) = v;
    }
    __syncthreads();

    // ---- Phase 2: emit output tile as float2 (never crosses a row).
    float* tout = out + ((size_t)b * T_DIM + t0) * ROW_F;   // 16B aligned

    #pragma unroll 4
    for (int i2 = tid; i2 < TILE_F2; i2 += NTHREADS) {
        const int fe   = i2 * 2;
        const int trow = fe / ROW_F;                       // mul-hi divide
        const float2 v = *reinterpret_cast<const float2*>(
            sm + fe - trow * (ROW_F - C_DIM));
        __stcs(reinterpret_cast<float2*>(tout + fe), v);   // streaming store
    }
}

extern "C" void kernel_launch(void* const* d_in, const int* in_sizes, int n_in,
                              void* d_out, int out_size)
{
    const float* x = (const float*)d_in[0];
    float* out = (float*)d_out;

    dim3 grid(T_DIM / TILE_T, B_DIM);     // 40 x 64 = 2560 blocks
    overlap_windows_kernel<<<grid, NTHREADS>>>(x, out);
}